// round 13
// baseline (speedup 1.0000x reference)
#include <cuda_runtime.h>
#include <math.h>

#define B_     16
#define L_     512
#define HID_   768
#define HEADS_ 12
#define EMB_   768
#define BLK_   8
#define NER_   6
#define NCLS_  97
#define XDIM_  1542            // 2*HID + NER
#define XP4_   1664            // padded k stride (13 * 128)
#define NCHUNK_ 16

// ---------------- scratch ----------------
__device__ float g_htp[B_*HEADS_*L_];
__device__ float g_hs [B_*HID_];
__device__ float g_ts [B_*HID_];
__device__ float g_rsp[NCHUNK_*B_*HID_];
__device__ float g_Sp [NCHUNK_*B_];
__device__ __align__(16) float g_x  [2*B_*XP4_];
__device__ __align__(16) float g_hs2[B_*EMB_];
__device__ __align__(16) float g_ts2[B_*EMB_];

__device__ __forceinline__ void l2_prefetch(const void* p) {
    asm volatile("prefetch.global.L2 [%0];" :: "l"(p));
}

// ======== K1: W prefetch + ht per-head partials + LSE (216 x 512) ========
__global__ void __launch_bounds__(512) k1(
    const float* __restrict__ seq, const float* __restrict__ attn,
    const int* __restrict__ epos,
    const float* __restrict__ Wh, const float* __restrict__ Wt,
    const float* __restrict__ Wb)
{
    const int idx = blockIdx.x*512 + threadIdx.x;   // < 110592 exactly

    // prologue: warm L2 with weight streams (async; overlaps everything)
    {
        const size_t wsz = (size_t)EMB_*XDIM_;                // 1,184,256
        for (size_t i = (size_t)idx*32; i < wsz; i += (size_t)110592*32) {
            l2_prefetch(Wh + i);
            l2_prefetch(Wt + i);
        }
        const size_t bsz = (size_t)NCLS_*EMB_*BLK_;           // 595,968
        for (size_t i = (size_t)idx*32; i < bsz; i += (size_t)110592*32)
            l2_prefetch(Wb + i);
    }

    if (idx < B_*HEADS_*L_) {
        const int l  = idx & (L_-1);
        const int bh = idx >> 9;
        const int b  = bh / HEADS_;
        const float* ah = attn + (size_t)bh * L_ * L_;
        float a0 = 0.f, a1 = 0.f;
#pragma unroll
        for (int m = 0; m < 4; m++) {
            const int s0 = __ldg(&epos[b*8 + m])     + 1;
            const int s1 = __ldg(&epos[b*8 + 4 + m]) + 1;
            a0 += __ldg(&ah[(size_t)s0*L_ + l]);
            a1 += __ldg(&ah[(size_t)s1*L_ + l]);
        }
        g_htp[idx] = a0 * a1 * (1.0f/192.0f);
    } else {
        const int r = idx - B_*HEADS_*L_;
        const int b = r / HID_;
        const int d = r - b*HID_;
        const float* seqb = seq + (size_t)b * L_ * HID_;
        float v0[4], v1[4];
#pragma unroll
        for (int m = 0; m < 4; m++) {
            const int s0 = __ldg(&epos[b*8 + m])     + 1;
            const int s1 = __ldg(&epos[b*8 + 4 + m]) + 1;
            v0[m] = __ldg(&seqb[(size_t)s0*HID_ + d]);
            v1[m] = __ldg(&seqb[(size_t)s1*HID_ + d]);
        }
        float mx0 = fmaxf(fmaxf(v0[0],v0[1]), fmaxf(v0[2],v0[3]));
        float mx1 = fmaxf(fmaxf(v1[0],v1[1]), fmaxf(v1[2],v1[3]));
        float e0 = __expf(v0[0]-mx0)+__expf(v0[1]-mx0)+__expf(v0[2]-mx0)+__expf(v0[3]-mx0);
        float e1 = __expf(v1[0]-mx1)+__expf(v1[1]-mx1)+__expf(v1[2]-mx1)+__expf(v1[3]-mx1);
        g_hs[b*HID_ + d] = mx0 + __logf(e0);
        g_ts[b*HID_ + d] = mx1 + __logf(e1);
    }
}

// ======== K2: rs chunk partials (grid = 256, 1 item/block) ========
__global__ void __launch_bounds__(512) k2(const float* __restrict__ seq)
{
    __shared__ float sp  [HEADS_*32];
    __shared__ float sht [32];
    __shared__ float pacc[4*768];

    const int tid   = threadIdx.x;
    const int item  = blockIdx.x;
    const int chunk = item / B_;
    const int b     = item % B_;

    if (tid < HEADS_*32) {
        const int hh  = tid >> 5;
        const int lid = tid & 31;
        sp[tid] = g_htp[(b*HEADS_ + hh)*L_ + chunk*32 + lid];
    }
    __syncthreads();
    if (tid < 32) {
        float s = 0.f;
#pragma unroll
        for (int hh = 0; hh < HEADS_; hh++) s += sp[hh*32 + tid];
        sht[tid] = s;
#pragma unroll
        for (int off = 16; off > 0; off >>= 1)
            s += __shfl_down_sync(0xffffffffu, s, off);
        if (tid == 0) g_Sp[item] = s;
    }
    __syncthreads();

    const int lg = tid >> 7;          // 4 groups of 8 rows
    const int dt = tid & 127;         // float2 column
    {
        const float* seqb = seq + ((size_t)b*L_ + chunk*32 + lg*8) * HID_;
        float2 a0 = {0.f,0.f}, a1 = {0.f,0.f}, a2 = {0.f,0.f};
#pragma unroll
        for (int l = 0; l < 8; l++) {
            const float w = sht[lg*8 + l];
            const float* row = seqb + (size_t)l * HID_;
            const float2 v0 = *(const float2*)&row[dt*2      ];
            const float2 v1 = *(const float2*)&row[dt*2 + 256];
            const float2 v2 = *(const float2*)&row[dt*2 + 512];
            a0.x = fmaf(v0.x, w, a0.x); a0.y = fmaf(v0.y, w, a0.y);
            a1.x = fmaf(v1.x, w, a1.x); a1.y = fmaf(v1.y, w, a1.y);
            a2.x = fmaf(v2.x, w, a2.x); a2.y = fmaf(v2.y, w, a2.y);
        }
        float* pp = pacc + lg*768;
        *(float2*)&pp[dt*2      ] = a0;
        *(float2*)&pp[dt*2 + 256] = a1;
        *(float2*)&pp[dt*2 + 512] = a2;
    }
    __syncthreads();
    {
        float* dst = g_rsp + (size_t)item * HID_;
        for (int i = tid; i < HID_; i += 512)
            dst[i] = (pacc[i] + pacc[768 + i]) + (pacc[1536 + i] + pacc[2304 + i]);
    }
}

// ======== K3: build g_x = [e | rs/(S+1e-5) | ner | 0-pad]  (104 x 512) ========
__global__ void __launch_bounds__(512) k3(
    const float* __restrict__ hs_ner, const float* __restrict__ ts_ner)
{
    const int idx = blockIdx.x*512 + threadIdx.x;    // < 53248 exactly
    const int half = idx / (B_*XP4_);
    const int rem  = idx - half*(B_*XP4_);
    const int b    = rem / XP4_;
    const int k    = rem - b*XP4_;
    float v = 0.f;
    if (k < HID_) {
        v = half ? g_ts[b*HID_ + k] : g_hs[b*HID_ + k];
    } else if (k < 2*HID_) {
        const int d = k - HID_;
        float acc = 0.f, S = 0.f;
#pragma unroll
        for (int c = 0; c < NCHUNK_; c++) {
            acc += g_rsp[((size_t)(c*B_ + b))*HID_ + d];
            S   += g_Sp[c*B_ + b];
        }
        v = acc / (S + 1e-5f);
    } else if (k < XDIM_) {
        const int d = k - 2*HID_;
        v = half ? __ldg(&ts_ner[b*NER_ + d]) : __ldg(&hs_ner[b*NER_ + d]);
    }
    g_x[idx] = v;
}

// ======== K4: hs2/ts2 = tanh(x @ W.T + b), W+x staged in smem ========
// grid = 192, 1 item/block: (half, 8-row tile), all 16 batches.
__global__ void __launch_bounds__(512, 1) k4(
    const float* __restrict__ Wh, const float* __restrict__ bh,
    const float* __restrict__ Wt, const float* __restrict__ bt)
{
    extern __shared__ float sm[];
    float* xsh = sm;                  // 16 * XP4_ = 26624 floats
    float* wsh = sm + B_*XP4_;        // 8 * XP4_  = 13312 floats
    float* red = sm + 24*XP4_;        // 256 floats

    const int tid   = threadIdx.x;
    const int item  = blockIdx.x;            // 0..191
    const int half  = item / 96;
    const int tile  = item % 96;
    const int obase = tile * 8;
    const float* Wsel = half ? Wt : Wh;
    const float* bias = half ? bt : bh;
    float*       outb = half ? g_ts2 : g_hs2;

    {   // x fill: all 16 batches, float4 (zero-pad already in g_x)
        const float* xsrc = g_x + (size_t)half * B_ * XP4_;
        for (int i = tid*4; i < B_*XP4_; i += 512*4)
            *(float4*)&xsh[i] = *(const float4*)&xsrc[i];
    }
    {   // W fill: 8 rows x 771 float2, coalesced, high MLP (L2-warm)
        const float* Wbase = Wsel + (size_t)obase * XDIM_;
        for (int i = tid; i < 8*771; i += 512) {
            const int r  = i / 771;
            const int k2 = i - r*771;
            *(float2*)&wsh[r*XP4_ + k2*2] =
                *(const float2*)&Wbase[(size_t)r*XDIM_ + k2*2];
        }
        for (int i = tid; i < 8*61; i += 512) {      // zero pad [XDIM_, XP4_)
            const int r = i / 61;
            const int p = i - r*61;
            *(float2*)&wsh[r*XP4_ + XDIM_ + p*2] = make_float2(0.f, 0.f);
        }
    }
    __syncthreads();

    {
        const int g  = tid >> 6;        // 0..7
        const int kt = tid & 63;        // 0..63 (2 warps per g)
        const int rh = g >> 1;          // 0..3 -> rows rh*2, rh*2+1
        const int bq = g & 1;           // 0..1 -> batches bq*8..bq*8+7

        float acc[2][8];
#pragma unroll
        for (int r = 0; r < 2; r++)
#pragma unroll
            for (int j = 0; j < 8; j++) acc[r][j] = 0.f;

        const float* xb = xsh + (size_t)(bq*8) * XP4_;
        const float* w0 = wsh + (size_t)(rh*2) * XP4_;
        const float* w1 = w0 + XP4_;
#pragma unroll
        for (int it = 0; it < 13; it++) {
            const int k = kt*2 + it*128;
            const float2 wv0 = *(const float2*)&w0[k];
            const float2 wv1 = *(const float2*)&w1[k];
#pragma unroll
            for (int j = 0; j < 8; j++) {
                const float2 xv = *(const float2*)&xb[j*XP4_ + k];
                acc[0][j] = fmaf(wv0.x, xv.x, fmaf(wv0.y, xv.y, acc[0][j]));
                acc[1][j] = fmaf(wv1.x, xv.x, fmaf(wv1.y, xv.y, acc[1][j]));
            }
        }
#pragma unroll
        for (int r = 0; r < 2; r++)
#pragma unroll
            for (int j = 0; j < 8; j++)
#pragma unroll
                for (int off = 16; off > 0; off >>= 1)
                    acc[r][j] += __shfl_down_sync(0xffffffffu, acc[r][j], off);
        if ((tid & 31) == 0) {
            const int w = tid >> 5;     // 0..15
#pragma unroll
            for (int r = 0; r < 2; r++)
#pragma unroll
                for (int j = 0; j < 8; j++)
                    red[w*16 + r*8 + j] = acc[r][j];
        }
    }
    __syncthreads();
    if (tid < 128) {
        const int ro = tid >> 4;       // 0..7 local row
        const int b  = tid & 15;       // batch
        const int rh = ro >> 1, rr = ro & 1;
        const int bq = b >> 3,  jj = b & 7;
        const int g  = rh*2 + bq;
        const float s = red[(2*g  )*16 + rr*8 + jj]
                      + red[(2*g+1)*16 + rr*8 + jj];
        const int o = obase + ro;
        outb[b*EMB_ + o] = tanhf(s + __ldg(&bias[o]));
    }
}

// ======== K5: logits (grid = 194, 1 (class, batch-half)/block) ========
__global__ void __launch_bounds__(512) k5(
    const float* __restrict__ Wb, const float* __restrict__ bb,
    float* __restrict__ out)
{
    extern __shared__ float sm[];
    float* hsh = sm;                   // 6144
    float* tsh = sm + 6144;            // 6144
    float* wsh = sm + 12288;           // 6144
    float* red = sm + 18432;           // 16*8

    const int tid  = threadIdx.x;
    const int item = blockIdx.x;
    const int c    = item >> 1;
    const int half = item & 1;

    {
        const float* hsrc = g_hs2 + half*8*EMB_;
        const float* tsrc = g_ts2 + half*8*EMB_;
        const float* Wc   = Wb + (size_t)c * (EMB_*BLK_);
        for (int i = tid*4; i < 8*EMB_; i += 512*4) {
            *(float4*)&hsh[i] = *(const float4*)&hsrc[i];
            *(float4*)&tsh[i] = *(const float4*)&tsrc[i];
            *(float4*)&wsh[i] = *(const float4*)&Wc[i];
        }
    }
    __syncthreads();
    {
        float acc[8];
#pragma unroll
        for (int b = 0; b < 8; b++) acc[b] = 0.f;
#pragma unroll
        for (int g = 0; g < 3; g++) {
            const int j = tid*4 + g*2048;
            const float4 wv = *(const float4*)&wsh[j];
            const int hidx  = j >> 3;
            const int tbase = ((j >> 6) << 3) | (j & 7);
#pragma unroll
            for (int b = 0; b < 8; b++) {
                const float  hv = hsh[b*EMB_ + hidx];
                const float4 tv = *(const float4*)&tsh[b*EMB_ + tbase];
                acc[b] = fmaf(wv.x, hv*tv.x, acc[b]);
                acc[b] = fmaf(wv.y, hv*tv.y, acc[b]);
                acc[b] = fmaf(wv.z, hv*tv.z, acc[b]);
                acc[b] = fmaf(wv.w, hv*tv.w, acc[b]);
            }
        }
#pragma unroll
        for (int b = 0; b < 8; b++)
#pragma unroll
            for (int off = 16; off > 0; off >>= 1)
                acc[b] += __shfl_down_sync(0xffffffffu, acc[b], off);
        if ((tid & 31) == 0) {
            const int w = tid >> 5;
#pragma unroll
            for (int b = 0; b < 8; b++) red[w*8 + b] = acc[b];
        }
    }
    __syncthreads();
    if (tid < 8) {
        float s = __ldg(&bb[c]);
#pragma unroll
        for (int w2 = 0; w2 < 16; w2++) s += red[w2*8 + tid];
        out[(half*8 + tid)*NCLS_ + c] = s;
    }
}

// ---------------- launch ----------------
extern "C" void kernel_launch(void* const* d_in, const int* in_sizes, int n_in,
                              void* d_out, int out_size)
{
    const float* seq    = (const float*)d_in[0];
    const float* attn   = (const float*)d_in[1];
    const int*   epos   = (const int*)  d_in[2];
    const float* hs_ner = (const float*)d_in[3];
    const float* ts_ner = (const float*)d_in[4];
    const float* Wh     = (const float*)d_in[5];
    const float* bh     = (const float*)d_in[6];
    const float* Wt     = (const float*)d_in[7];
    const float* bt     = (const float*)d_in[8];
    const float* Wb     = (const float*)d_in[9];
    const float* bb     = (const float*)d_in[10];
    float* out = (float*)d_out;

    const int smem_k4 = (24*XP4_ + 256) * 4;        // 160,768 B
    const int smem_k5 = (18432 + 128) * 4;          //  74,240 B
    cudaFuncSetAttribute(k4, cudaFuncAttributeMaxDynamicSharedMemorySize, smem_k4);
    cudaFuncSetAttribute(k5, cudaFuncAttributeMaxDynamicSharedMemorySize, smem_k5);

    k1<<<216, 512>>>(seq, attn, epos, Wh, Wt, Wb);  // 216*512 = 110592 exact
    k2<<<NCHUNK_*B_, 512>>>(seq);                   // 256 blocks
    k3<<<104, 512>>>(hs_ner, ts_ner);               // 104*512 = 53248 exact
    k4<<<192, 512, smem_k4>>>(Wh, bh, Wt, bt);
    k5<<<2*NCLS_, 512, smem_k5>>>(Wb, bb, out);
}

// round 14
// speedup vs baseline: 1.3137x; 1.3137x over previous
#include <cuda_runtime.h>
#include <math.h>

#define B_     16
#define L_     512
#define HID_   768
#define HEADS_ 12
#define EMB_   768
#define BLK_   8
#define NER_   6
#define NCLS_  97
#define XDIM_  1542            // 2*HID + NER
#define XP_    1664            // padded k stride (13 * 128)
#define NCHUNK_ 16
#define NT_    512

// ---------------- scratch ----------------
__device__ float g_htp[B_*HEADS_*L_];
__device__ __align__(16) float g_hs [B_*HID_];
__device__ __align__(16) float g_ts [B_*HID_];
__device__ float g_rsp[NCHUNK_*B_*HID_];
__device__ float g_Sp [NCHUNK_*B_];
__device__ __align__(16) float g_rsN[B_*HID_];    // normalized rs
__device__ __align__(16) float g_hs2[B_*EMB_];
__device__ __align__(16) float g_ts2[B_*EMB_];
__device__ unsigned long long g_bar = 0ULL;

// Monotonic ticket barrier. Arrival = one RMW; spin = acquire LOADS only.
__device__ __forceinline__ void grid_barrier() {
    __syncthreads();
    if (threadIdx.x == 0) {
        __threadfence();
        const unsigned long long nb  = gridDim.x;
        const unsigned long long pos = atomicAdd(&g_bar, 1ULL);
        const unsigned long long target = (pos / nb + 1ULL) * nb;
        unsigned long long v = pos + 1ULL;
        while (v < target) {
            asm volatile("ld.acquire.gpu.u64 %0, [%1];"
                         : "=l"(v) : "l"(&g_bar) : "memory");
            if (v < target) __nanosleep(128);
        }
    }
    __syncthreads();
}

__device__ __forceinline__ void l2_prefetch(const void* p) {
    asm volatile("prefetch.global.L2 [%0];" :: "l"(p));
}

__global__ void __launch_bounds__(NT_, 2) fused_kernel(
    const float* __restrict__ seq,  const float* __restrict__ attn,
    const int*   __restrict__ epos,
    const float* __restrict__ hs_ner, const float* __restrict__ ts_ner,
    const float* __restrict__ Wh, const float* __restrict__ bh,
    const float* __restrict__ Wt, const float* __restrict__ bt,
    const float* __restrict__ Wb, const float* __restrict__ bb,
    float* __restrict__ out)
{
    extern __shared__ float sm[];
    const int tid = threadIdx.x;
    const int nb  = gridDim.x;

    // ======== P0: warm L2 with the weight streams ========
    {
        const int gt  = blockIdx.x*NT_ + tid;
        const int gn  = nb*NT_;
        const size_t wsz = (size_t)EMB_*XDIM_;
        for (size_t i = (size_t)gt*32; i < wsz; i += (size_t)gn*32) {
            l2_prefetch(Wh + i);
            l2_prefetch(Wt + i);
        }
        const size_t bsz = (size_t)NCLS_*EMB_*BLK_;
        for (size_t i = (size_t)gt*32; i < bsz; i += (size_t)gn*32)
            l2_prefetch(Wb + i);
    }

    // ======== P1: ht per-head partials + LSE embeddings ========
    {
        const int tot = B_*HEADS_*L_ + B_*HID_;
        for (int idx = blockIdx.x*NT_ + tid; idx < tot; idx += nb*NT_) {
            if (idx < B_*HEADS_*L_) {
                const int l  = idx & (L_-1);
                const int bh = idx >> 9;
                const int b  = bh / HEADS_;
                const float* ah = attn + (size_t)bh * L_ * L_;
                float a0 = 0.f, a1 = 0.f;
#pragma unroll
                for (int m = 0; m < 4; m++) {
                    const int s0 = __ldg(&epos[b*8 + m])     + 1;
                    const int s1 = __ldg(&epos[b*8 + 4 + m]) + 1;
                    a0 += __ldg(&ah[(size_t)s0*L_ + l]);
                    a1 += __ldg(&ah[(size_t)s1*L_ + l]);
                }
                g_htp[idx] = a0 * a1 * (1.0f/192.0f);
            } else {
                const int r = idx - B_*HEADS_*L_;
                const int b = r / HID_;
                const int d = r - b*HID_;
                const float* seqb = seq + (size_t)b * L_ * HID_;
                float v0[4], v1[4];
#pragma unroll
                for (int m = 0; m < 4; m++) {
                    const int s0 = __ldg(&epos[b*8 + m])     + 1;
                    const int s1 = __ldg(&epos[b*8 + 4 + m]) + 1;
                    v0[m] = __ldg(&seqb[(size_t)s0*HID_ + d]);
                    v1[m] = __ldg(&seqb[(size_t)s1*HID_ + d]);
                }
                float mx0 = fmaxf(fmaxf(v0[0],v0[1]), fmaxf(v0[2],v0[3]));
                float mx1 = fmaxf(fmaxf(v1[0],v1[1]), fmaxf(v1[2],v1[3]));
                float e0 = __expf(v0[0]-mx0)+__expf(v0[1]-mx0)+__expf(v0[2]-mx0)+__expf(v0[3]-mx0);
                float e1 = __expf(v1[0]-mx1)+__expf(v1[1]-mx1)+__expf(v1[2]-mx1)+__expf(v1[3]-mx1);
                g_hs[b*HID_ + d] = mx0 + __logf(e0);
                g_ts[b*HID_ + d] = mx1 + __logf(e1);
            }
        }
    }
    grid_barrier();

    // ======== P2: rs chunk partials (256 items, float2, 4 l-subgroups) ========
    {
        float* sht  = sm;          // 32
        float* pacc = sm + 32;     // 4*768
        const int lg = tid >> 7;
        const int dt = tid & 127;
        for (int item = blockIdx.x; item < NCHUNK_*B_; item += nb) {
            const int chunk = item / B_;
            const int b     = item % B_;
            __syncthreads();
            if (tid < 32) {
                const int l = chunk*32 + tid;
                float acc = 0.f;
#pragma unroll
                for (int h = 0; h < HEADS_; h++)
                    acc += g_htp[(b*HEADS_ + h)*L_ + l];
                sht[tid] = acc;
                float s = acc;
#pragma unroll
                for (int off = 16; off > 0; off >>= 1)
                    s += __shfl_down_sync(0xffffffffu, s, off);
                if (tid == 0) g_Sp[item] = s;
            }
            __syncthreads();
            {
                const float* seqb = seq + ((size_t)b*L_ + chunk*32 + lg*8) * HID_;
                float2 a0 = {0.f,0.f}, a1 = {0.f,0.f}, a2 = {0.f,0.f};
#pragma unroll
                for (int l = 0; l < 8; l++) {
                    const float w = sht[lg*8 + l];
                    const float* row = seqb + (size_t)l * HID_;
                    const float2 v0 = *(const float2*)&row[dt*2      ];
                    const float2 v1 = *(const float2*)&row[dt*2 + 256];
                    const float2 v2 = *(const float2*)&row[dt*2 + 512];
                    a0.x = fmaf(v0.x, w, a0.x); a0.y = fmaf(v0.y, w, a0.y);
                    a1.x = fmaf(v1.x, w, a1.x); a1.y = fmaf(v1.y, w, a1.y);
                    a2.x = fmaf(v2.x, w, a2.x); a2.y = fmaf(v2.y, w, a2.y);
                }
                float* pp = pacc + lg*768;
                *(float2*)&pp[dt*2      ] = a0;
                *(float2*)&pp[dt*2 + 256] = a1;
                *(float2*)&pp[dt*2 + 512] = a2;
            }
            __syncthreads();
            {
                float* dst = g_rsp + (size_t)item * HID_;
                for (int i = tid; i < HID_; i += NT_)
                    dst[i] = (pacc[i] + pacc[768 + i])
                           + (pacc[1536 + i] + pacc[2304 + i]);
            }
        }
    }
    grid_barrier();

    // ======== P3: g_rsN[b][d] = (sum_c rsp)/(S+1e-5)  (12288 items) ========
    for (int idx = blockIdx.x*NT_ + tid; idx < B_*HID_; idx += nb*NT_) {
        const int b = idx / HID_;
        const int d = idx - b*HID_;
        float acc = 0.f, S = 0.f;
#pragma unroll
        for (int c = 0; c < NCHUNK_; c++) {
            acc += g_rsp[((size_t)(c*B_ + b))*HID_ + d];
            S   += g_Sp[c*B_ + b];
        }
        g_rsN[idx] = acc / (S + 1e-5f);
    }
    grid_barrier();

    // ======== P4: hs2/ts2 = tanh(x @ W.T + b) ========
    // 192 items: (half, 8-row tile), all 16 batches. 1 item per CTA (nb >= 192).
    // Thread tile acc[4 rows][4 batches]; k split over 64 lanes (2 warps).
    {
        float* xsh = sm;                // 16 * XP_ = 26624 floats
        float* red = sm + B_*XP_;       // 8 groups * 2 warps * 16 = 256 floats
        const int item = blockIdx.x;
        if (item < 192) {
            const int half  = item / 96;
            const int tile  = item % 96;
            const int obase = tile * 8;
            const float* Wsel = half ? Wt : Wh;
            const float* bias = half ? bt : bh;
            const float* esrc = half ? g_ts : g_hs;
            const float* ner  = half ? ts_ner : hs_ner;
            float*       outb = half ? g_ts2 : g_hs2;

            // x fill: x = [e | rsN | ner | 0-pad], 16 batches, float4 segments
            for (int i = tid*4; i < B_*XP_; i += NT_*4) {
                const int b = i / XP_;
                const int k = i - b*XP_;
                float4 v;
                if (k < HID_) {
                    v = *(const float4*)&esrc[b*HID_ + k];
                } else if (k < 2*HID_) {
                    v = *(const float4*)&g_rsN[b*HID_ + (k - HID_)];
                } else {
                    float t[4];
#pragma unroll
                    for (int q = 0; q < 4; q++) {
                        const int kk = k + q;
                        t[q] = (kk < XDIM_) ? __ldg(&ner[b*NER_ + (kk - 2*HID_)]) : 0.f;
                    }
                    v = make_float4(t[0], t[1], t[2], t[3]);
                }
                *(float4*)&xsh[i] = v;
            }
            __syncthreads();

            {
                const int g  = tid >> 6;        // 0..7
                const int kt = tid & 63;        // 0..63
                const int rh = g >> 2;          // 0..1 -> rows rh*4 .. +3
                const int bq = g & 3;           // 0..3 -> batches bq*4 .. +3

                float acc[4][4];
#pragma unroll
                for (int r = 0; r < 4; r++)
#pragma unroll
                    for (int j = 0; j < 4; j++) acc[r][j] = 0.f;

                const float* xb = xsh + (size_t)(bq*4) * XP_;
                const float* Wbase = Wsel + (size_t)(obase + rh*4) * XDIM_;
#pragma unroll
                for (int it = 0; it < 13; it++) {
                    const int k = kt*2 + it*128;
                    float2 wv[4];
#pragma unroll
                    for (int r = 0; r < 4; r++) {
                        wv[r] = (k < XDIM_)
                              ? *(const float2*)&Wbase[(size_t)r*XDIM_ + k]
                              : make_float2(0.f, 0.f);
                    }
#pragma unroll
                    for (int j = 0; j < 4; j++) {
                        const float2 xv = *(const float2*)&xb[j*XP_ + k];
#pragma unroll
                        for (int r = 0; r < 4; r++)
                            acc[r][j] = fmaf(wv[r].x, xv.x,
                                        fmaf(wv[r].y, xv.y, acc[r][j]));
                    }
                }
#pragma unroll
                for (int r = 0; r < 4; r++)
#pragma unroll
                    for (int j = 0; j < 4; j++)
#pragma unroll
                        for (int off = 16; off > 0; off >>= 1)
                            acc[r][j] += __shfl_down_sync(0xffffffffu, acc[r][j], off);
                if ((tid & 31) == 0) {
                    const int wsub = (tid >> 5) & 1;       // which warp of the group
                    float* rg = red + (g*2 + wsub)*16;
#pragma unroll
                    for (int r = 0; r < 4; r++)
#pragma unroll
                        for (int j = 0; j < 4; j++)
                            rg[r*4 + j] = acc[r][j];
                }
            }
            __syncthreads();
            if (tid < 128) {
                const int ro = tid >> 4;       // 0..7 local row
                const int b  = tid & 15;       // batch
                const int rh = ro >> 2, r = ro & 3;
                const int bq = b >> 2,  jj = b & 3;
                const int g  = rh*4 + bq;
                const float s = red[(g*2    )*16 + r*4 + jj]
                              + red[(g*2 + 1)*16 + r*4 + jj];
                const int o = obase + ro;
                outb[b*EMB_ + o] = tanhf(s + __ldg(&bias[o]));
            }
        }
    }
    grid_barrier();

    // ======== P5: logits (194 (class, batch-half) items) ========
    {
        float* hsh = sm;                   // 6144
        float* tsh = sm + 6144;            // 6144
        float* wsh = sm + 12288;           // 6144
        float* red = sm + 18432;           // 16*8
        for (int item = blockIdx.x; item < 2*NCLS_; item += nb) {
            const int c    = item >> 1;
            const int half = item & 1;
            __syncthreads();
            {
                const float* hsrc = g_hs2 + half*8*EMB_;
                const float* tsrc = g_ts2 + half*8*EMB_;
                const float* Wc   = Wb + (size_t)c * (EMB_*BLK_);
                for (int i = tid*4; i < 8*EMB_; i += NT_*4) {
                    *(float4*)&hsh[i] = *(const float4*)&hsrc[i];
                    *(float4*)&tsh[i] = *(const float4*)&tsrc[i];
                    *(float4*)&wsh[i] = *(const float4*)&Wc[i];
                }
            }
            __syncthreads();
            {
                float acc[8];
#pragma unroll
                for (int b = 0; b < 8; b++) acc[b] = 0.f;
#pragma unroll
                for (int g = 0; g < 3; g++) {
                    const int j = tid*4 + g*2048;
                    const float4 wv = *(const float4*)&wsh[j];
                    const int hidx  = j >> 3;
                    const int tbase = ((j >> 6) << 3) | (j & 7);
#pragma unroll
                    for (int b = 0; b < 8; b++) {
                        const float  hv = hsh[b*EMB_ + hidx];
                        const float4 tv = *(const float4*)&tsh[b*EMB_ + tbase];
                        acc[b] = fmaf(wv.x, hv*tv.x, acc[b]);
                        acc[b] = fmaf(wv.y, hv*tv.y, acc[b]);
                        acc[b] = fmaf(wv.z, hv*tv.z, acc[b]);
                        acc[b] = fmaf(wv.w, hv*tv.w, acc[b]);
                    }
                }
#pragma unroll
                for (int b = 0; b < 8; b++)
#pragma unroll
                    for (int off = 16; off > 0; off >>= 1)
                        acc[b] += __shfl_down_sync(0xffffffffu, acc[b], off);
                if ((tid & 31) == 0) {
                    const int w = tid >> 5;
#pragma unroll
                    for (int b = 0; b < 8; b++) red[w*8 + b] = acc[b];
                }
            }
            __syncthreads();
            if (tid < 8) {
                float s = __ldg(&bb[c]);
#pragma unroll
                for (int w2 = 0; w2 < 16; w2++) s += red[w2*8 + tid];
                out[(half*8 + tid)*NCLS_ + c] = s;
            }
        }
    }
}

// ---------------- launch ----------------
extern "C" void kernel_launch(void* const* d_in, const int* in_sizes, int n_in,
                              void* d_out, int out_size)
{
    const float* seq    = (const float*)d_in[0];
    const float* attn   = (const float*)d_in[1];
    const int*   epos   = (const int*)  d_in[2];
    const float* hs_ner = (const float*)d_in[3];
    const float* ts_ner = (const float*)d_in[4];
    const float* Wh     = (const float*)d_in[5];
    const float* bh     = (const float*)d_in[6];
    const float* Wt     = (const float*)d_in[7];
    const float* bt     = (const float*)d_in[8];
    const float* Wb     = (const float*)d_in[9];
    const float* bb     = (const float*)d_in[10];
    float* out = (float*)d_out;

    const int smem = (B_*XP_ + 256) * 4;   // 107,520 B (P4 max; P5 needs 74 KB)
    cudaFuncSetAttribute(fused_kernel, cudaFuncAttributeMaxDynamicSharedMemorySize, smem);

    int nsm = 148;
    cudaDeviceGetAttribute(&nsm, cudaDevAttrMultiProcessorCount, 0);
    int bpm = 1;
    cudaOccupancyMaxActiveBlocksPerMultiprocessor(&bpm, fused_kernel, NT_, smem);
    if (bpm < 1) bpm = 1;
    const int nb = nsm * bpm;   // all CTAs co-resident => grid barrier safe

    fused_kernel<<<nb, NT_, smem>>>(seq, attn, epos, hs_ner, ts_ner,
                                    Wh, bh, Wt, bt, Wb, bb, out);
}

// round 15
// speedup vs baseline: 1.4227x; 1.0830x over previous
#include <cuda_runtime.h>
#include <math.h>

#define B_     16
#define L_     512
#define HID_   768
#define HEADS_ 12
#define EMB_   768
#define BLK_   8
#define NER_   6
#define NCLS_  97
#define XDIM_  1542            // 2*HID + NER
#define XP_    1664            // padded k stride (13 * 128)
#define NCHUNK_ 16
#define NT_    512

// ---------------- scratch ----------------
__device__ __align__(16) float g_hs [B_*HID_];
__device__ __align__(16) float g_ts [B_*HID_];
__device__ float g_rsp[NCHUNK_*B_*HID_];
__device__ float g_Sp [NCHUNK_*B_];
__device__ __align__(16) float g_rsN[B_*HID_];    // normalized rs
__device__ __align__(16) float g_hs2[B_*EMB_];
__device__ __align__(16) float g_ts2[B_*EMB_];
__device__ unsigned long long g_bar = 0ULL;

// Monotonic ticket barrier. Arrival = one RMW; spin = acquire LOADS only.
__device__ __forceinline__ void grid_barrier() {
    __syncthreads();
    if (threadIdx.x == 0) {
        __threadfence();
        const unsigned long long nb  = gridDim.x;
        const unsigned long long pos = atomicAdd(&g_bar, 1ULL);
        const unsigned long long target = (pos / nb + 1ULL) * nb;
        unsigned long long v = pos + 1ULL;
        while (v < target) {
            asm volatile("ld.acquire.gpu.u64 %0, [%1];"
                         : "=l"(v) : "l"(&g_bar) : "memory");
            if (v < target) __nanosleep(64);
        }
    }
    __syncthreads();
}

__device__ __forceinline__ void l2_prefetch(const void* p) {
    asm volatile("prefetch.global.L2 [%0];" :: "l"(p));
}

__global__ void __launch_bounds__(NT_, 2) fused_kernel(
    const float* __restrict__ seq,  const float* __restrict__ attn,
    const int*   __restrict__ epos,
    const float* __restrict__ hs_ner, const float* __restrict__ ts_ner,
    const float* __restrict__ Wh, const float* __restrict__ bh,
    const float* __restrict__ Wt, const float* __restrict__ bt,
    const float* __restrict__ Wb, const float* __restrict__ bb,
    float* __restrict__ out)
{
    extern __shared__ float sm[];
    const int tid = threadIdx.x;
    const int nb  = gridDim.x;

    // ======== P0: warm L2 with the weight streams ========
    {
        const int gt  = blockIdx.x*NT_ + tid;
        const int gn  = nb*NT_;
        const size_t wsz = (size_t)EMB_*XDIM_;
        for (size_t i = (size_t)gt*32; i < wsz; i += (size_t)gn*32) {
            l2_prefetch(Wh + i);
            l2_prefetch(Wt + i);
        }
        const size_t bsz = (size_t)NCLS_*EMB_*BLK_;
        for (size_t i = (size_t)gt*32; i < bsz; i += (size_t)gn*32)
            l2_prefetch(Wb + i);
    }

    // ======== PA (merged P1+P2): blocks 0..255 -> (chunk,b) item:
    //            in-block ht from attention, then rs chunk partial.
    //          blocks 256..279 -> LSE embeddings (12288 items). ========
    {
        float* sp   = sm;           // 384: per-(h,l) partials
        float* sht  = sm + 384;     // 32
        float* pacc = sm + 416;     // 4*768
        const int item = blockIdx.x;
        if (item < NCHUNK_*B_) {
            const int chunk = item >> 4;     // item / 16
            const int b     = item & 15;     // item % 16
            int s0[4], s1[4];
#pragma unroll
            for (int m = 0; m < 4; m++) {
                s0[m] = __ldg(&epos[b*8 + m])     + 1;
                s1[m] = __ldg(&epos[b*8 + 4 + m]) + 1;
            }
            // step 1: per-(h,l) attention gather (384 threads, 8 loads each)
            if (tid < HEADS_*32) {
                const int h = tid >> 5;
                const int l = chunk*32 + (tid & 31);
                const float* ah = attn + ((size_t)(b*HEADS_ + h) * L_) * L_;
                float a0 = 0.f, a1 = 0.f;
#pragma unroll
                for (int m = 0; m < 4; m++) {
                    a0 += __ldg(&ah[(size_t)s0[m]*L_ + l]);
                    a1 += __ldg(&ah[(size_t)s1[m]*L_ + l]);
                }
                sp[tid] = a0 * a1 * (1.0f/192.0f);
            }
            __syncthreads();
            // step 2: reduce over heads + chunk sum
            if (tid < 32) {
                float s = 0.f;
#pragma unroll
                for (int h = 0; h < HEADS_; h++) s += sp[h*32 + tid];
                sht[tid] = s;
#pragma unroll
                for (int off = 16; off > 0; off >>= 1)
                    s += __shfl_down_sync(0xffffffffu, s, off);
                if (tid == 0) g_Sp[item] = s;
            }
            __syncthreads();
            // step 3: rs chunk partial (float2, 4 l-subgroups)
            {
                const int lg = tid >> 7;
                const int dt = tid & 127;
                const float* seqb = seq + ((size_t)b*L_ + chunk*32 + lg*8) * HID_;
                float2 a0 = {0.f,0.f}, a1 = {0.f,0.f}, a2 = {0.f,0.f};
#pragma unroll
                for (int l = 0; l < 8; l++) {
                    const float w = sht[lg*8 + l];
                    const float* row = seqb + (size_t)l * HID_;
                    const float2 v0 = *(const float2*)&row[dt*2      ];
                    const float2 v1 = *(const float2*)&row[dt*2 + 256];
                    const float2 v2 = *(const float2*)&row[dt*2 + 512];
                    a0.x = fmaf(v0.x, w, a0.x); a0.y = fmaf(v0.y, w, a0.y);
                    a1.x = fmaf(v1.x, w, a1.x); a1.y = fmaf(v1.y, w, a1.y);
                    a2.x = fmaf(v2.x, w, a2.x); a2.y = fmaf(v2.y, w, a2.y);
                }
                float* pp = pacc + lg*768;
                *(float2*)&pp[dt*2      ] = a0;
                *(float2*)&pp[dt*2 + 256] = a1;
                *(float2*)&pp[dt*2 + 512] = a2;
            }
            __syncthreads();
            {
                float* dst = g_rsp + (size_t)item * HID_;
                for (int i = tid; i < HID_; i += NT_)
                    dst[i] = (pacc[i] + pacc[768 + i])
                           + (pacc[1536 + i] + pacc[2304 + i]);
            }
        } else {
            // LSE embeddings: idx in [0, 12288)
            const int idx = (item - NCHUNK_*B_)*NT_ + tid;
            if (idx < B_*HID_) {
                const int b = idx / HID_;
                const int d = idx - b*HID_;
                const float* seqb = seq + (size_t)b * L_ * HID_;
                float v0[4], v1[4];
#pragma unroll
                for (int m = 0; m < 4; m++) {
                    const int s0 = __ldg(&epos[b*8 + m])     + 1;
                    const int s1 = __ldg(&epos[b*8 + 4 + m]) + 1;
                    v0[m] = __ldg(&seqb[(size_t)s0*HID_ + d]);
                    v1[m] = __ldg(&seqb[(size_t)s1*HID_ + d]);
                }
                float mx0 = fmaxf(fmaxf(v0[0],v0[1]), fmaxf(v0[2],v0[3]));
                float mx1 = fmaxf(fmaxf(v1[0],v1[1]), fmaxf(v1[2],v1[3]));
                float e0 = __expf(v0[0]-mx0)+__expf(v0[1]-mx0)+__expf(v0[2]-mx0)+__expf(v0[3]-mx0);
                float e1 = __expf(v1[0]-mx1)+__expf(v1[1]-mx1)+__expf(v1[2]-mx1)+__expf(v1[3]-mx1);
                g_hs[b*HID_ + d] = mx0 + __logf(e0);
                g_ts[b*HID_ + d] = mx1 + __logf(e1);
            }
        }
    }
    grid_barrier();

    // ======== P3: g_rsN[b][d] = (sum_c rsp)/(S+1e-5)  (12288 items) ========
    for (int idx = blockIdx.x*NT_ + tid; idx < B_*HID_; idx += nb*NT_) {
        const int b = idx / HID_;
        const int d = idx - b*HID_;
        float acc = 0.f, S = 0.f;
#pragma unroll
        for (int c = 0; c < NCHUNK_; c++) {
            acc += g_rsp[((size_t)(c*B_ + b))*HID_ + d];
            S   += g_Sp[c*B_ + b];
        }
        g_rsN[idx] = acc / (S + 1e-5f);
    }
    grid_barrier();

    // ======== P4: hs2/ts2 = tanh(x @ W.T + b) ========
    // 192 items: (half, 8-row tile), all 16 batches. 1 item per CTA (nb >= 192).
    {
        float* xsh = sm;                // 16 * XP_ = 26624 floats
        float* red = sm + B_*XP_;       // 256 floats
        const int item = blockIdx.x;
        if (item < 192) {
            const int half  = item / 96;
            const int tile  = item % 96;
            const int obase = tile * 8;
            const float* Wsel = half ? Wt : Wh;
            const float* bias = half ? bt : bh;
            const float* esrc = half ? g_ts : g_hs;
            const float* ner  = half ? ts_ner : hs_ner;
            float*       outb = half ? g_ts2 : g_hs2;

            // x fill: x = [e | rsN | ner | 0-pad], 16 batches, float4 segments
            for (int i = tid*4; i < B_*XP_; i += NT_*4) {
                const int b = i / XP_;
                const int k = i - b*XP_;
                float4 v;
                if (k < HID_) {
                    v = *(const float4*)&esrc[b*HID_ + k];
                } else if (k < 2*HID_) {
                    v = *(const float4*)&g_rsN[b*HID_ + (k - HID_)];
                } else {
                    float t[4];
#pragma unroll
                    for (int q = 0; q < 4; q++) {
                        const int kk = k + q;
                        t[q] = (kk < XDIM_) ? __ldg(&ner[b*NER_ + (kk - 2*HID_)]) : 0.f;
                    }
                    v = make_float4(t[0], t[1], t[2], t[3]);
                }
                *(float4*)&xsh[i] = v;
            }
            __syncthreads();

            {
                const int g  = tid >> 6;        // 0..7
                const int kt = tid & 63;        // 0..63
                const int rh = g >> 2;          // 0..1 -> rows rh*4 .. +3
                const int bq = g & 3;           // 0..3 -> batches bq*4 .. +3

                float acc[4][4];
#pragma unroll
                for (int r = 0; r < 4; r++)
#pragma unroll
                    for (int j = 0; j < 4; j++) acc[r][j] = 0.f;

                const float* xb = xsh + (size_t)(bq*4) * XP_;
                const float* Wbase = Wsel + (size_t)(obase + rh*4) * XDIM_;
#pragma unroll
                for (int it = 0; it < 13; it++) {
                    const int k = kt*2 + it*128;
                    float2 wv[4];
#pragma unroll
                    for (int r = 0; r < 4; r++) {
                        wv[r] = (k < XDIM_)
                              ? *(const float2*)&Wbase[(size_t)r*XDIM_ + k]
                              : make_float2(0.f, 0.f);
                    }
#pragma unroll
                    for (int j = 0; j < 4; j++) {
                        const float2 xv = *(const float2*)&xb[j*XP_ + k];
#pragma unroll
                        for (int r = 0; r < 4; r++)
                            acc[r][j] = fmaf(wv[r].x, xv.x,
                                        fmaf(wv[r].y, xv.y, acc[r][j]));
                    }
                }
#pragma unroll
                for (int r = 0; r < 4; r++)
#pragma unroll
                    for (int j = 0; j < 4; j++)
#pragma unroll
                        for (int off = 16; off > 0; off >>= 1)
                            acc[r][j] += __shfl_down_sync(0xffffffffu, acc[r][j], off);
                if ((tid & 31) == 0) {
                    const int wsub = (tid >> 5) & 1;
                    float* rg = red + (g*2 + wsub)*16;
#pragma unroll
                    for (int r = 0; r < 4; r++)
#pragma unroll
                        for (int j = 0; j < 4; j++)
                            rg[r*4 + j] = acc[r][j];
                }
            }
            __syncthreads();
            if (tid < 128) {
                const int ro = tid >> 4;       // 0..7 local row
                const int b  = tid & 15;       // batch
                const int rh = ro >> 2, r = ro & 3;
                const int bq = b >> 2,  jj = b & 3;
                const int g  = rh*4 + bq;
                const float s = red[(g*2    )*16 + r*4 + jj]
                              + red[(g*2 + 1)*16 + r*4 + jj];
                const int o = obase + ro;
                outb[b*EMB_ + o] = tanhf(s + __ldg(&bias[o]));
            }
        }
    }
    grid_barrier();

    // ======== P5: logits (194 (class, batch-half) items) ========
    {
        float* hsh = sm;                   // 6144
        float* tsh = sm + 6144;            // 6144
        float* wsh = sm + 12288;           // 6144
        float* red = sm + 18432;           // 16*8
        for (int item = blockIdx.x; item < 2*NCLS_; item += nb) {
            const int c    = item >> 1;
            const int half = item & 1;
            __syncthreads();
            {
                const float* hsrc = g_hs2 + half*8*EMB_;
                const float* tsrc = g_ts2 + half*8*EMB_;
                const float* Wc   = Wb + (size_t)c * (EMB_*BLK_);
                for (int i = tid*4; i < 8*EMB_; i += NT_*4) {
                    *(float4*)&hsh[i] = *(const float4*)&hsrc[i];
                    *(float4*)&tsh[i] = *(const float4*)&tsrc[i];
                    *(float4*)&wsh[i] = *(const float4*)&Wc[i];
                }
            }
            __syncthreads();
            {
                float acc[8];
#pragma unroll
                for (int b = 0; b < 8; b++) acc[b] = 0.f;
#pragma unroll
                for (int g = 0; g < 3; g++) {
                    const int j = tid*4 + g*2048;
                    const float4 wv = *(const float4*)&wsh[j];
                    const int hidx  = j >> 3;
                    const int tbase = ((j >> 6) << 3) | (j & 7);
#pragma unroll
                    for (int b = 0; b < 8; b++) {
                        const float  hv = hsh[b*EMB_ + hidx];
                        const float4 tv = *(const float4*)&tsh[b*EMB_ + tbase];
                        acc[b] = fmaf(wv.x, hv*tv.x, acc[b]);
                        acc[b] = fmaf(wv.y, hv*tv.y, acc[b]);
                        acc[b] = fmaf(wv.z, hv*tv.z, acc[b]);
                        acc[b] = fmaf(wv.w, hv*tv.w, acc[b]);
                    }
                }
#pragma unroll
                for (int b = 0; b < 8; b++)
#pragma unroll
                    for (int off = 16; off > 0; off >>= 1)
                        acc[b] += __shfl_down_sync(0xffffffffu, acc[b], off);
                if ((tid & 31) == 0) {
                    const int w = tid >> 5;
#pragma unroll
                    for (int b = 0; b < 8; b++) red[w*8 + b] = acc[b];
                }
            }
            __syncthreads();
            if (tid < 8) {
                float s = __ldg(&bb[c]);
#pragma unroll
                for (int w2 = 0; w2 < 16; w2++) s += red[w2*8 + tid];
                out[(half*8 + tid)*NCLS_ + c] = s;
            }
        }
    }
}

// ---------------- launch ----------------
extern "C" void kernel_launch(void* const* d_in, const int* in_sizes, int n_in,
                              void* d_out, int out_size)
{
    const float* seq    = (const float*)d_in[0];
    const float* attn   = (const float*)d_in[1];
    const int*   epos   = (const int*)  d_in[2];
    const float* hs_ner = (const float*)d_in[3];
    const float* ts_ner = (const float*)d_in[4];
    const float* Wh     = (const float*)d_in[5];
    const float* bh     = (const float*)d_in[6];
    const float* Wt     = (const float*)d_in[7];
    const float* bt     = (const float*)d_in[8];
    const float* Wb     = (const float*)d_in[9];
    const float* bb     = (const float*)d_in[10];
    float* out = (float*)d_out;

    const int smem = (B_*XP_ + 256) * 4;   // 107,520 B (P4 max)
    cudaFuncSetAttribute(fused_kernel, cudaFuncAttributeMaxDynamicSharedMemorySize, smem);

    int nsm = 148;
    cudaDeviceGetAttribute(&nsm, cudaDevAttrMultiProcessorCount, 0);
    int bpm = 1;
    cudaOccupancyMaxActiveBlocksPerMultiprocessor(&bpm, fused_kernel, NT_, smem);
    if (bpm < 1) bpm = 1;
    int nb = nsm * bpm;          // all CTAs co-resident => grid barrier safe
    if (nb < 280) nb = 280;      // PA requires 256 chunk items + 24 LSE blocks

    fused_kernel<<<nb, NT_, smem>>>(seq, attn, epos, hs_ner, ts_ner,
                                    Wh, bh, Wt, bt, Wb, bb, out);
}